// round 6
// baseline (speedup 1.0000x reference)
#include <cuda_runtime.h>

#define MARGIN 0.2f
#define TPB   256
#define TILE  256
#define NWARP (TPB / 32)
#define NB    64
#define MAXN  16384
#define MAXBLK (MAXN / TPB)

__device__ double g_rank_sum;
__device__ double g_m[5];          // sum_p, sum_p2, sum_t, sum_t2, sum_diff2
__device__ unsigned int g_done;
__device__ int   g_bh[MAXBLK * NB];   // per-(chunk, bucket) offsets
__device__ int   g_bstart[NB + 1];    // global bucket starts (+ sentinel n)
__device__ int   g_btmin[NB];         // bucket t-min (float bits, t >= 0)
__device__ int   g_btmax[NB];         // bucket t-max (float bits)
__device__ float g_ps[MAXN];          // predictions, bucket-reordered
__device__ float g_tt[MAXN];          // targets, bucket-reordered

__device__ __forceinline__ int bucket_of(float t) {
    int b = (int)(t * (float)NB);
    return min(NB - 1, max(0, b));
}

// ---------------------------------------------------------------------------
// 0) init accumulators (g_bh is fully overwritten later; no zeroing needed)
// ---------------------------------------------------------------------------
__global__ void init_kernel() {
    int i = threadIdx.x;
    if (i < NB) { g_btmin[i] = 0x7F7FFFFF; g_btmax[i] = 0; }
    if (i == NB)     g_rank_sum = 0.0;
    if (i == NB + 1) g_done = 0u;
    if (i >= NB + 2 && i < NB + 7) g_m[i - NB - 2] = 0.0;
}

// ---------------------------------------------------------------------------
// 1) per-chunk bucket histogram + bucket t-min/max + O(N) moments
// ---------------------------------------------------------------------------
__global__ __launch_bounds__(TPB) void histmom_kernel(const float* __restrict__ pr,
                                                      const float* __restrict__ tg,
                                                      int n) {
    __shared__ int    shist[NB], smin[NB], smax[NB];
    __shared__ double smom[5][NWARP];
    const int tid = threadIdx.x, lane = tid & 31, wid = tid >> 5;
    const int blk = blockIdx.x;
    const int idx = blk * TPB + tid;

    for (int q = tid; q < NB; q += TPB) {
        shist[q] = 0; smin[q] = 0x7F7FFFFF; smax[q] = 0;
    }
    __syncthreads();

    double m[5] = {0, 0, 0, 0, 0};
    if (idx < n) {
        float p = pr[idx], t = tg[idx];
        int b = bucket_of(t);
        atomicAdd(&shist[b], 1);
        int tb = __float_as_int(t);     // t >= 0: int order == float order
        atomicMin(&smin[b], tb);
        atomicMax(&smax[b], tb);
        double pv = (double)p, tv = (double)t, d = pv - tv;
        m[0] = pv; m[1] = pv * pv; m[2] = tv; m[3] = tv * tv; m[4] = d * d;
    }
    #pragma unroll
    for (int q = 0; q < 5; q++) {
        #pragma unroll
        for (int o = 16; o > 0; o >>= 1)
            m[q] += __shfl_down_sync(0xFFFFFFFFu, m[q], o);
        if (lane == 0) smom[q][wid] = m[q];
    }
    __syncthreads();
    if (wid == 0) {
        #pragma unroll
        for (int q = 0; q < 5; q++) {
            double v = (lane < NWARP) ? smom[q][lane] : 0.0;
            #pragma unroll
            for (int o = 4; o > 0; o >>= 1)
                v += __shfl_down_sync(0xFFFFFFFFu, v, o);
            if (lane == 0) atomicAdd(&g_m[q], v);
        }
    }
    for (int q = tid; q < NB; q += TPB) {
        g_bh[blk * NB + q] = shist[q];
        if (shist[q]) {
            atomicMin(&g_btmin[q], smin[q]);
            atomicMax(&g_btmax[q], smax[q]);
        }
    }
}

// ---------------------------------------------------------------------------
// 2) offsets: per-bucket prefix across chunks, then bucket bases
// ---------------------------------------------------------------------------
__global__ void offsets_kernel(int n, int nblk) {
    __shared__ int tot[NB], base[NB];
    int b = threadIdx.x;
    if (b < NB) {
        int vals[MAXBLK];
        #pragma unroll 8
        for (int k = 0; k < nblk; k++) vals[k] = g_bh[k * NB + b];  // MLP
        int s = 0;
        for (int k = 0; k < nblk; k++) { int t = vals[k]; vals[k] = s; s += t; }
        tot[b] = s;
        __syncthreads();
        if (b == 0) {
            int acc = 0;
            for (int q = 0; q < NB; q++) { base[q] = acc; g_bstart[q] = acc; acc += tot[q]; }
            g_bstart[NB] = n;
        }
        __syncthreads();
        int bb = base[b];
        for (int k = 0; k < nblk; k++) g_bh[k * NB + b] = vals[k] + bb;
    } else {
        __syncthreads();
        __syncthreads();
    }
}

// ---------------------------------------------------------------------------
// 3) scatter with ballot-based stable rank (O(NWARP) per thread)
// ---------------------------------------------------------------------------
__global__ __launch_bounds__(TPB) void scatter_kernel(const float* __restrict__ pr,
                                                      const float* __restrict__ tg,
                                                      int n) {
    __shared__ int scnt[NWARP][NB];
    const int tid = threadIdx.x, lane = tid & 31, wid = tid >> 5;
    const int blk = blockIdx.x;
    const int idx = blk * TPB + tid;
    const bool valid = idx < n;

    for (int q = tid; q < NWARP * NB; q += TPB) ((int*)scnt)[q] = 0;
    __syncthreads();

    float t = valid ? tg[idx] : 0.f;
    float p = valid ? pr[idx] : 0.f;
    int myb = valid ? bucket_of(t) : NB + lane;  // invalid: harmless groups
    unsigned peers = __match_any_sync(0xFFFFFFFFu, myb);
    int lrank = __popc(peers & ((1u << lane) - 1u));
    if (valid && lrank == 0) scnt[wid][myb] = __popc(peers);  // leader writes
    __syncthreads();
    if (valid) {
        int rank = lrank;
        #pragma unroll
        for (int w = 0; w < NWARP; w++)
            if (w < wid) rank += scnt[w][myb];
        int pos = g_bh[blk * NB + myb] + rank;
        g_ps[pos] = p;
        g_tt[pos] = t;
    }
}

// ---------------------------------------------------------------------------
// 4) triangular pair kernel: unified |p - theta| loop + closed-form linear
//    term. Diagonal blocks compute the full tile-square and halve (per_pair
//    is i<->j symmetric; self-pairs are exactly 0).
// ---------------------------------------------------------------------------
__global__ __launch_bounds__(TPB) void pair_kernel(int n, int G, int T,
                                                   float* __restrict__ out) {
    const int b = blockIdx.x;
    double disc = (double)(2 * G + 1) * (double)(2 * G + 1) - 8.0 * (double)b;
    int r = (int)(((double)(2 * G + 1) - sqrt(disc)) * 0.5);
    while (r > 0 && (r * G - (r * (r - 1)) / 2) > b) --r;
    while (((r + 1) * G - ((r + 1) * r) / 2) <= b) ++r;
    const int c = r + (b - (r * G - (r * (r - 1)) / 2));
    const bool diag = (c == r);

    __shared__ __align__(16) float sp[TILE];
    __shared__ float  stt[TILE];
    __shared__ float  ssum[NB];
    __shared__ int    sbs[NB + 1];
    __shared__ float  sbmin[NB], sbmax[NB];
    __shared__ double swarp[NWARP];
    __shared__ int    s_bf, s_bl;
    __shared__ bool   s_last;

    const int tid = threadIdx.x, lane = tid & 31, wid = tid >> 5;
    const int j0 = c * TILE;
    const int jcnt = min(TILE, n - j0);
    const int jend = j0 + jcnt;

    if (tid < NB) {
        ssum[tid]  = 0.f;
        sbmin[tid] = __int_as_float(g_btmin[tid]);
        sbmax[tid] = __int_as_float(g_btmax[tid]);
    }
    if (tid < NB + 1) sbs[tid] = g_bstart[tid];
    float tj = 0.f, pj = 0.f;
    if (tid < jcnt) {
        pj = g_ps[j0 + tid];
        tj = g_tt[j0 + tid];
        sp[tid]  = pj;
        stt[tid] = tj;
    }
    __syncthreads();
    if (tid < jcnt) atomicAdd(&ssum[bucket_of(tj)], pj);   // per-segment p sum
    if (tid < NB) {
        if (sbs[tid] <= j0 && j0 < sbs[tid + 1]) s_bf = tid;
        if (sbs[tid] < jend && jend <= sbs[tid + 1]) s_bl = tid;
    }
    __syncthreads();
    const int bf = s_bf, bl = s_bl;

    const int  i  = r * TILE + tid;
    const bool vi = (i < n);
    const float p0 = vi ? g_ps[i] : 0.f;
    const float t0 = vi ? g_tt[i] : 0.f;

    float facc = 0.f;   // Σ|v - θ| over hinge segments (needs ×0.5)
    float lin  = 0.f;   // closed-form linear hinge part (needs ×0.5)
    float macc = 0.f;   // Σ|dp| over mid pairs (needs ×0.1)
    float eacc = 0.f;   // exact hinge values from boundary segments (×1)

    if (vi) {
        for (int bb = bf; bb <= bl; bb++) {
            const int lo = max(sbs[bb] - j0, 0);
            const int hi = min(sbs[bb + 1] - j0, jcnt);
            if (lo >= hi) continue;
            const float dtmax = t0 - sbmin[bb];   // >= every fl(t0-tj) in seg
            const float dtmin = t0 - sbmax[bb];   // <= every fl(t0-tj) in seg
            const bool  is_hi  = (dtmin > MARGIN);
            const bool  is_lo  = (dtmax < -MARGIN);
            const bool  is_mid = (dtmax <= MARGIN) && (dtmin >= -MARGIN);

            if (is_hi | is_lo | is_mid) {
                const float cntf = (float)(hi - lo);
                const float S    = ssum[bb];
                float theta;
                if (is_hi)      { theta = p0 - MARGIN; lin += S - cntf * theta; }
                else if (is_lo) { theta = p0 + MARGIN; lin += cntf * theta - S; }
                else            { theta = p0; }

                float a0 = 0.f, a1 = 0.f, a2 = 0.f, a3 = 0.f;
                int k = lo;
                for (; k < hi && (k & 3); k++) a0 += fabsf(sp[k] - theta);
                for (; k + 4 <= hi; k += 4) {
                    float4 v = *reinterpret_cast<const float4*>(&sp[k]);
                    a0 += fabsf(v.x - theta);
                    a1 += fabsf(v.y - theta);
                    a2 += fabsf(v.z - theta);
                    a3 += fabsf(v.w - theta);
                }
                for (; k < hi; k++) a0 += fabsf(sp[k] - theta);
                float aseg = (a0 + a1) + (a2 + a3);
                if (is_mid) macc += aseg;
                else        facc += aseg;
            } else {
                // boundary bucket: reference-exact per-pair predicates
                #pragma unroll 4
                for (int k = lo; k < hi; k++) {
                    float dp = p0 - sp[k];
                    float dt = t0 - stt[k];
                    float u  = __uint_as_float(__float_as_uint(dp) ^
                               (__float_as_uint(dt) & 0x80000000u));
                    float h  = fmaxf(MARGIN - u, 0.0f);
                    if (fabsf(dt) > MARGIN) eacc += h;
                    else                    macc += fabsf(dp);
                }
            }
        }
    }

    double mine = 0.5 * ((double)facc + (double)lin)
                + (double)eacc + 0.1 * (double)macc;
    if (diag) mine *= 0.5;   // full tile-square computed; self-pairs are 0

    #pragma unroll
    for (int o = 16; o > 0; o >>= 1)
        mine += __shfl_down_sync(0xFFFFFFFFu, mine, o);
    if (lane == 0) swarp[wid] = mine;
    __syncthreads();

    if (wid == 0) {
        double v = (lane < NWARP) ? swarp[lane] : 0.0;
        #pragma unroll
        for (int o = 4; o > 0; o >>= 1)
            v += __shfl_down_sync(0xFFFFFFFFu, v, o);
        if (lane == 0) atomicAdd(&g_rank_sum, v);
    }

    if (tid == 0) {
        __threadfence();
        unsigned int prev = atomicAdd(&g_done, 1u);
        s_last = (prev == (unsigned int)(T - 1));
    }
    __syncthreads();

    if (s_last && tid == 0) {
        double sm  = g_m[0], sp2 = g_m[1], st = g_m[2], st2 = g_m[3], sd2 = g_m[4];
        double nn = (double)n;
        double mse  = sd2 / nn;
        double pvar = (sp2 - sm * sm / nn) / (nn - 1.0);
        double tvar = (st2 - st * st / nn) / (nn - 1.0);
        double divl = fmax(tvar - pvar, 0.0);
        double pc   = nn * (nn - 1.0) * 0.5;
        double rank = g_rank_sum / pc;
        out[0] = (float)(0.1 * mse + 0.9 * rank + 0.1 * divl);
    }
}

extern "C" void kernel_launch(void* const* d_in, const int* in_sizes, int n_in,
                              void* d_out, int out_size) {
    const float* pred = (const float*)d_in[0];
    const float* targ = (const float*)d_in[1];
    int n = in_sizes[0];
    int nblk = (n + TPB - 1) / TPB;

    init_kernel<<<1, 128>>>();
    histmom_kernel<<<nblk, TPB>>>(pred, targ, n);
    offsets_kernel<<<1, NB>>>(n, nblk);
    scatter_kernel<<<nblk, TPB>>>(pred, targ, n);

    int G = (n + TILE - 1) / TILE;
    int T = G * (G + 1) / 2;
    pair_kernel<<<T, TPB>>>(n, G, T, (float*)d_out);
}

// round 7
// speedup vs baseline: 1.0008x; 1.0008x over previous
#include <cuda_runtime.h>
#include <cstdint>

#define MARGIN 0.2f
#define TPB   256
#define TILE  256
#define NWARP (TPB / 32)
#define NB    64
#define MAXN  16384
#define MAXBLK (MAXN / TPB)

__device__ double g_rank_sum;
__device__ double g_m[5];
__device__ unsigned int g_done;
__device__ unsigned int g_syncA, g_syncA2;
__device__ int    g_cnt[MAXBLK * NB];
__device__ int    g_minp[MAXBLK * NB];
__device__ int    g_maxp[MAXBLK * NB];
__device__ double g_mompart[MAXBLK * 5];
__device__ int    g_bstart[NB + 1];
__device__ int    g_btmin[NB];
__device__ int    g_btmax[NB];
__device__ float  g_ps[MAXN];
__device__ float  g_tt[MAXN];

__device__ __forceinline__ int bucket_of(float t) {
    int b = (int)(t * (float)NB);
    return min(NB - 1, max(0, b));
}

// ===========================================================================
// Kernel A: ALL preprocessing in one launch (32 blocks, in-kernel barrier).
// ===========================================================================
__global__ __launch_bounds__(TPB) void prep_kernel(const float* __restrict__ pr,
                                                   const float* __restrict__ tg,
                                                   int n, int nblk) {
    __shared__ int    shist[NB], smin_[NB], smax_[NB];
    __shared__ int    stot[NB], sbase[NB + 1], schunk[NB];
    __shared__ int    scnt[NWARP][NB];
    __shared__ double smom[5][NWARP];

    const int tid = threadIdx.x, lane = tid & 31, wid = tid >> 5;
    const int blk = blockIdx.x;
    const int idx = blk * TPB + tid;
    const bool valid = idx < n;

    for (int q = tid; q < NB; q += TPB) {
        shist[q] = 0; smin_[q] = 0x7F7FFFFF; smax_[q] = 0;
    }
    for (int q = tid; q < NWARP * NB; q += TPB) ((int*)scnt)[q] = 0;
    __syncthreads();

    // ---- phase 1: chunk histogram + min/max + moment partials ----
    float p = 0.f, t = 0.f;
    int myb = NB + lane;            // invalid threads: distinct harmless keys
    double m[5] = {0, 0, 0, 0, 0};
    if (valid) {
        p = pr[idx]; t = tg[idx];
        myb = bucket_of(t);
        atomicAdd(&shist[myb], 1);
        int tb = __float_as_int(t);     // t >= 0: int order == float order
        atomicMin(&smin_[myb], tb);
        atomicMax(&smax_[myb], tb);
        double pv = (double)p, tv = (double)t, d = pv - tv;
        m[0] = pv; m[1] = pv * pv; m[2] = tv; m[3] = tv * tv; m[4] = d * d;
    }
    #pragma unroll
    for (int q = 0; q < 5; q++) {
        #pragma unroll
        for (int o = 16; o > 0; o >>= 1)
            m[q] += __shfl_down_sync(0xFFFFFFFFu, m[q], o);
        if (lane == 0) smom[q][wid] = m[q];
    }
    __syncthreads();
    if (wid == 0) {
        #pragma unroll
        for (int q = 0; q < 5; q++) {
            double v = (lane < NWARP) ? smom[q][lane] : 0.0;
            #pragma unroll
            for (int o = 4; o > 0; o >>= 1)
                v += __shfl_down_sync(0xFFFFFFFFu, v, o);
            if (lane == 0) g_mompart[blk * 5 + q] = v;
        }
    }
    if (tid < NB) {
        g_cnt[blk * NB + tid]  = shist[tid];
        g_minp[blk * NB + tid] = smin_[tid];
        g_maxp[blk * NB + tid] = smax_[tid];
    }
    __threadfence();
    __syncthreads();

    // ---- grid barrier (all nblk blocks resident; nblk <= 64) ----
    if (tid == 0) {
        atomicAdd(&g_syncA, 1u);
        while (*(volatile unsigned*)&g_syncA < (unsigned)nblk) {}
        __threadfence();
    }
    __syncthreads();

    // ---- phase 2: offsets (every block computes its own) ----
    int myoff = 0;
    if (tid < NB) {
        int tot = 0;
        for (int k = 0; k < nblk; k++) {
            int v = g_cnt[k * NB + tid];
            if (k < blk) myoff += v;
            tot += v;
        }
        stot[tid] = tot;
    }
    __syncthreads();
    if (tid == 0) {
        int s = 0;
        #pragma unroll
        for (int q = 0; q < NB; q++) { sbase[q] = s; s += stot[q]; }
        sbase[NB] = s;
    }
    __syncthreads();
    if (tid < NB) schunk[tid] = sbase[tid] + myoff;

    if (blk == 0) {   // publish global tables + zero pair-kernel accumulators
        if (tid < NB) {
            int mn = 0x7F7FFFFF, mx = 0;
            for (int k = 0; k < nblk; k++) {
                mn = min(mn, g_minp[k * NB + tid]);
                mx = max(mx, g_maxp[k * NB + tid]);
            }
            g_btmin[tid] = mn;
            g_btmax[tid] = mx;
            g_bstart[tid] = sbase[tid];
        }
        if (tid == NB) g_bstart[NB] = n;
        if (tid >= NB + 1 && tid < NB + 6) {
            int q = tid - NB - 1;
            double s = 0.0;
            for (int k = 0; k < nblk; k++) s += g_mompart[k * 5 + q];
            g_m[q] = s;
        }
        if (tid == NB + 6) g_rank_sum = 0.0;
        if (tid == NB + 7) g_done = 0u;
    }

    // ---- phase 3: stable scatter via match_any rank ----
    unsigned peers = __match_any_sync(0xFFFFFFFFu, myb);
    int lrank = __popc(peers & ((1u << lane) - 1u));
    if (valid && lrank == 0) scnt[wid][myb] = __popc(peers);
    __syncthreads();
    if (valid) {
        int rank = lrank;
        #pragma unroll
        for (int w = 0; w < NWARP; w++)
            if (w < wid) rank += scnt[w][myb];
        int pos = schunk[myb] + rank;
        g_ps[pos] = p;
        g_tt[pos] = t;
    }

    // ---- exit: reset barrier counters for graph replay ----
    __threadfence();
    __syncthreads();
    if (tid == 0) {
        unsigned v = atomicAdd(&g_syncA2, 1u);
        if (v == (unsigned)nblk - 1u) { g_syncA = 0u; g_syncA2 = 0u; }
    }
}

// ===========================================================================
// Kernel B: triangular pair kernel, |p - theta| unified loop (f32x2 packed)
// + closed-form linear term + finalize.
// ===========================================================================
__global__ __launch_bounds__(TPB) void pair_kernel(int n, int G, int T,
                                                   float* __restrict__ out) {
    const int b = blockIdx.x;
    double disc = (double)(2 * G + 1) * (double)(2 * G + 1) - 8.0 * (double)b;
    int r = (int)(((double)(2 * G + 1) - sqrt(disc)) * 0.5);
    while (r > 0 && (r * G - (r * (r - 1)) / 2) > b) --r;
    while (((r + 1) * G - ((r + 1) * r) / 2) <= b) ++r;
    const int c = r + (b - (r * G - (r * (r - 1)) / 2));
    const bool diag = (c == r);

    __shared__ __align__(16) float sp[TILE];
    __shared__ float  stt[TILE];
    __shared__ float  ssum[NB];
    __shared__ int    sbs[NB + 1];
    __shared__ float  sbmin[NB], sbmax[NB];
    __shared__ double swarp[NWARP];
    __shared__ int    s_bf, s_bl;
    __shared__ bool   s_last;

    const int tid = threadIdx.x, lane = tid & 31, wid = tid >> 5;
    const int j0 = c * TILE;
    const int jcnt = min(TILE, n - j0);
    const int jend = j0 + jcnt;

    if (tid < NB) {
        ssum[tid]  = 0.f;
        sbmin[tid] = __int_as_float(g_btmin[tid]);
        sbmax[tid] = __int_as_float(g_btmax[tid]);
    }
    if (tid < NB + 1) sbs[tid] = g_bstart[tid];
    float tj = 0.f, pj = 0.f;
    if (tid < jcnt) {
        pj = g_ps[j0 + tid];
        tj = g_tt[j0 + tid];
        sp[tid]  = pj;
        stt[tid] = tj;
    }
    __syncthreads();
    if (tid < jcnt) atomicAdd(&ssum[bucket_of(tj)], pj);
    if (tid < NB) {
        if (sbs[tid] <= j0 && j0 < sbs[tid + 1]) s_bf = tid;
        if (sbs[tid] < jend && jend <= sbs[tid + 1]) s_bl = tid;
    }
    __syncthreads();
    const int bf = s_bf, bl = s_bl;

    const int  i  = r * TILE + tid;
    const bool vi = (i < n);
    const float p0 = vi ? g_ps[i] : 0.f;
    const float t0 = vi ? g_tt[i] : 0.f;

    float facc = 0.f;   // Σ|v - θ| over hinge segments (×0.5)
    float lin  = 0.f;   // closed-form linear hinge part (×0.5)
    float macc = 0.f;   // Σ|dp| over mid pairs (×0.1)
    float eacc = 0.f;   // exact boundary-segment hinge values (×1)

    if (vi) {
        for (int bb = bf; bb <= bl; bb++) {
            const int lo = max(sbs[bb] - j0, 0);
            const int hi = min(sbs[bb + 1] - j0, jcnt);
            if (lo >= hi) continue;
            const float dtmax = t0 - sbmin[bb];
            const float dtmin = t0 - sbmax[bb];
            const bool  is_hi  = (dtmin > MARGIN);
            const bool  is_lo  = (dtmax < -MARGIN);
            const bool  is_mid = (dtmax <= MARGIN) && (dtmin >= -MARGIN);

            if (is_hi | is_lo | is_mid) {
                const float cntf = (float)(hi - lo);
                const float S    = ssum[bb];
                float theta;
                if (is_hi)      { theta = p0 - MARGIN; lin += S - cntf * theta; }
                else if (is_lo) { theta = p0 + MARGIN; lin += cntf * theta - S; }
                else            { theta = p0; }

                // packed f32x2: 1 fma-pipe + 1 alu-pipe op per pair
                uint64_t nth2, acc01 = 0ull, acc23 = 0ull;
                {
                    uint32_t nb_ = __float_as_uint(-theta);
                    asm("mov.b64 %0, {%1, %1};" : "=l"(nth2) : "r"(nb_));
                }
                float a0 = 0.f;
                int k = lo;
                for (; k < hi && (k & 3); k++) a0 += fabsf(sp[k] - theta);
                for (; k + 4 <= hi; k += 4) {
                    float4 v = *reinterpret_cast<const float4*>(&sp[k]);
                    uint64_t v01, v23, d01, d23;
                    asm("mov.b64 %0, {%1, %2};" : "=l"(v01)
                        : "r"(__float_as_uint(v.x)), "r"(__float_as_uint(v.y)));
                    asm("mov.b64 %0, {%1, %2};" : "=l"(v23)
                        : "r"(__float_as_uint(v.z)), "r"(__float_as_uint(v.w)));
                    asm("add.rn.f32x2 %0, %1, %2;" : "=l"(d01) : "l"(v01), "l"(nth2));
                    asm("add.rn.f32x2 %0, %1, %2;" : "=l"(d23) : "l"(v23), "l"(nth2));
                    d01 &= 0x7FFFFFFF7FFFFFFFull;
                    d23 &= 0x7FFFFFFF7FFFFFFFull;
                    asm("add.rn.f32x2 %0, %1, %2;" : "=l"(acc01) : "l"(acc01), "l"(d01));
                    asm("add.rn.f32x2 %0, %1, %2;" : "=l"(acc23) : "l"(acc23), "l"(d23));
                }
                for (; k < hi; k++) a0 += fabsf(sp[k] - theta);
                uint32_t u0, u1, u2, u3;
                asm("mov.b64 {%0, %1}, %2;" : "=r"(u0), "=r"(u1) : "l"(acc01));
                asm("mov.b64 {%0, %1}, %2;" : "=r"(u2), "=r"(u3) : "l"(acc23));
                float aseg = a0 + (__uint_as_float(u0) + __uint_as_float(u1))
                                + (__uint_as_float(u2) + __uint_as_float(u3));
                if (is_mid) macc += aseg;
                else        facc += aseg;
            } else {
                // boundary bucket: reference-exact per-pair predicates
                #pragma unroll 4
                for (int k = lo; k < hi; k++) {
                    float dp = p0 - sp[k];
                    float dt = t0 - stt[k];
                    float u  = __uint_as_float(__float_as_uint(dp) ^
                               (__float_as_uint(dt) & 0x80000000u));
                    float h  = fmaxf(MARGIN - u, 0.0f);
                    if (fabsf(dt) > MARGIN) eacc += h;
                    else                    macc += fabsf(dp);
                }
            }
        }
    }

    double mine = 0.5 * ((double)facc + (double)lin)
                + (double)eacc + 0.1 * (double)macc;
    if (diag) mine *= 0.5;   // full tile-square computed; self-pairs are 0

    #pragma unroll
    for (int o = 16; o > 0; o >>= 1)
        mine += __shfl_down_sync(0xFFFFFFFFu, mine, o);
    if (lane == 0) swarp[wid] = mine;
    __syncthreads();

    if (wid == 0) {
        double v = (lane < NWARP) ? swarp[lane] : 0.0;
        #pragma unroll
        for (int o = 4; o > 0; o >>= 1)
            v += __shfl_down_sync(0xFFFFFFFFu, v, o);
        if (lane == 0) atomicAdd(&g_rank_sum, v);
    }

    if (tid == 0) {
        __threadfence();
        unsigned int prev = atomicAdd(&g_done, 1u);
        s_last = (prev == (unsigned int)(T - 1));
    }
    __syncthreads();

    if (s_last && tid == 0) {
        double sm  = g_m[0], sp2 = g_m[1], st = g_m[2], st2 = g_m[3], sd2 = g_m[4];
        double nn = (double)n;
        double mse  = sd2 / nn;
        double pvar = (sp2 - sm * sm / nn) / (nn - 1.0);
        double tvar = (st2 - st * st / nn) / (nn - 1.0);
        double divl = fmax(tvar - pvar, 0.0);
        double pc   = nn * (nn - 1.0) * 0.5;
        double rank = g_rank_sum / pc;
        out[0] = (float)(0.1 * mse + 0.9 * rank + 0.1 * divl);
    }
}

extern "C" void kernel_launch(void* const* d_in, const int* in_sizes, int n_in,
                              void* d_out, int out_size) {
    const float* pred = (const float*)d_in[0];
    const float* targ = (const float*)d_in[1];
    int n = in_sizes[0];
    int nblk = (n + TPB - 1) / TPB;

    prep_kernel<<<nblk, TPB>>>(pred, targ, n, nblk);

    int G = (n + TILE - 1) / TILE;
    int T = G * (G + 1) / 2;
    pair_kernel<<<T, TPB>>>(n, G, T, (float*)d_out);
}

// round 8
// speedup vs baseline: 1.1079x; 1.1070x over previous
#include <cuda_runtime.h>

#define MARGIN 0.2f
#define TPB   256
#define TILE  256
#define NWARP 8
#define NB    64
#define MAXN  16384
#define MAXG  (MAXN / TILE)
#define GRIDN 264

__device__ double g_rank_sum;
__device__ double g_m[5];
__device__ unsigned int g_done;
__device__ unsigned int g_bar;
__device__ int    g_cnt[MAXG * NB];
__device__ double g_mompart[MAXG * 5];
__device__ float  g_ps[MAXN], g_tt[MAXN];
__device__ float  g_spt[MAXG][TILE];      // per-tile p, sorted ascending
__device__ float  g_pfx[MAXG][TILE + 1];  // exclusive prefix sums of sorted p
__device__ float  g_tmn[MAXG], g_tmx[MAXG];

__device__ __forceinline__ int bucket_of(float t) {
    int b = (int)(t * (float)NB);
    return min(NB - 1, max(0, b));
}

__global__ __launch_bounds__(TPB, 2)
void fused_kernel(const float* __restrict__ pr, const float* __restrict__ tg,
                  int n, int G, int T, float* __restrict__ out) {
    __shared__ int    s_hist[NB];
    __shared__ int    s_stot[NB], s_sbase[NB], s_schunk[NB];
    __shared__ int    s_scnt[NWARP][NB];
    __shared__ double s_md[5][NWARP];
    __shared__ float  s_wf[NWARP], s_wf2[NWARP];
    __shared__ double s_wd[NWARP];
    __shared__ __align__(16) float s_a[TILE];     // sorted p of j-tile
    __shared__ float  s_pfx[TILE + 1];
    __shared__ float  s_rp[TILE], s_rt[TILE];     // raw j-tile (p, t)

    const int tid = threadIdx.x, lane = tid & 31, wid = tid >> 5;
    const int bid = blockIdx.x;
    const unsigned NBLK = gridDim.x;

    // ================= phase 1: chunk histogram + moments =================
    float p = 0.f, t = 0.f;
    bool valid = false;
    int myb = 0;
    if (bid < G) {
        for (int q = tid; q < NB; q += TPB) s_hist[q] = 0;
        for (int q = tid; q < NWARP * NB; q += TPB) ((int*)s_scnt)[q] = 0;
        __syncthreads();
        int idx = bid * TPB + tid;
        valid = idx < n;
        double m[5] = {0, 0, 0, 0, 0};
        if (valid) {
            p = pr[idx]; t = tg[idx];
            myb = bucket_of(t);
            atomicAdd(&s_hist[myb], 1);
            double pv = (double)p, tv = (double)t, d = pv - tv;
            m[0] = pv; m[1] = pv * pv; m[2] = tv; m[3] = tv * tv; m[4] = d * d;
        }
        #pragma unroll
        for (int q = 0; q < 5; q++) {
            #pragma unroll
            for (int o = 16; o > 0; o >>= 1)
                m[q] += __shfl_down_sync(0xFFFFFFFFu, m[q], o);
            if (lane == 0) s_md[q][wid] = m[q];
        }
        __syncthreads();
        if (wid == 0) {
            #pragma unroll
            for (int q = 0; q < 5; q++) {
                double v = (lane < NWARP) ? s_md[q][lane] : 0.0;
                #pragma unroll
                for (int o = 4; o > 0; o >>= 1)
                    v += __shfl_down_sync(0xFFFFFFFFu, v, o);
                if (lane == 0) g_mompart[bid * 5 + q] = v;
            }
        }
        if (tid < NB) g_cnt[bid * NB + tid] = s_hist[tid];
    }

    // ---- grid barrier 1 ----
    __syncthreads();
    if (tid == 0) { __threadfence(); atomicAdd(&g_bar, 1u);
        while (*(volatile unsigned*)&g_bar < NBLK) {} __threadfence(); }
    __syncthreads();

    // ================= phase 2: offsets + scatter (bucket sort) ===========
    if (bid < G) {
        int myoff = 0;
        if (tid < NB) {
            int tot = 0;
            for (int k = 0; k < G; k++) {
                int v = g_cnt[k * NB + tid];
                if (k < bid) myoff += v;
                tot += v;
            }
            s_stot[tid] = tot;
        }
        __syncthreads();
        if (tid == 0) {
            int s = 0;
            #pragma unroll
            for (int q = 0; q < NB; q++) { s_sbase[q] = s; s += s_stot[q]; }
        }
        __syncthreads();
        if (tid < NB) s_schunk[tid] = s_sbase[tid] + myoff;
        if (bid == 0) {
            if (tid >= 64 && tid < 69) {
                int q = tid - 64;
                double s = 0.0;
                for (int k = 0; k < G; k++) s += g_mompart[k * 5 + q];
                g_m[q] = s;
            }
            if (tid == 69) g_rank_sum = 0.0;
            if (tid == 70) g_done = 0u;
        }
        __syncthreads();
        int key = valid ? myb : NB + lane;
        unsigned peers = __match_any_sync(0xFFFFFFFFu, key);
        int lrank = __popc(peers & ((1u << lane) - 1u));
        if (valid && lrank == 0) s_scnt[wid][myb] = __popc(peers);
        __syncthreads();
        if (valid) {
            int rank = lrank;
            #pragma unroll
            for (int w = 0; w < NWARP; w++)
                if (w < wid) rank += s_scnt[w][myb];
            int pos = s_schunk[myb] + rank;
            g_ps[pos] = p;
            g_tt[pos] = t;
        }
    }

    // ---- grid barrier 2 ----
    __syncthreads();
    if (tid == 0) { __threadfence(); atomicAdd(&g_bar, 1u);
        while (*(volatile unsigned*)&g_bar < 2u * NBLK) {} __threadfence(); }
    __syncthreads();

    // ======== phase 3: per-tile p-sort (bitonic) + prefix + t-bounds ======
    if (bid < G) {
        int base = bid * TILE;
        int cnt = min(TILE, n - base);
        bool v = tid < cnt;
        float pv = v ? g_ps[base + tid] : __int_as_float(0x7F800000);  // +inf pad
        float tv = v ? g_tt[base + tid] : 0.f;
        s_a[tid] = pv;
        float tmn = v ? tv : 3.0e38f, tmx = v ? tv : -3.0e38f;
        #pragma unroll
        for (int o = 16; o > 0; o >>= 1) {
            tmn = fminf(tmn, __shfl_xor_sync(0xFFFFFFFFu, tmn, o));
            tmx = fmaxf(tmx, __shfl_xor_sync(0xFFFFFFFFu, tmx, o));
        }
        if (lane == 0) { s_wf[wid] = tmn; s_wf2[wid] = tmx; }
        __syncthreads();
        if (tid == 0) {
            float a = s_wf[0], b2 = s_wf2[0];
            #pragma unroll
            for (int w = 1; w < NWARP; w++) {
                a = fminf(a, s_wf[w]); b2 = fmaxf(b2, s_wf2[w]);
            }
            g_tmn[bid] = a; g_tmx[bid] = b2;
        }
        __syncthreads();
        // bitonic sort s_a ascending (256 elems, 256 threads)
        for (int k2 = 2; k2 <= TILE; k2 <<= 1) {
            for (int j = k2 >> 1; j > 0; j >>= 1) {
                int ixj = tid ^ j;
                if (ixj > tid) {
                    float a = s_a[tid], b2 = s_a[ixj];
                    bool up = ((tid & k2) == 0);
                    if ((a > b2) == up) { s_a[tid] = b2; s_a[ixj] = a; }
                }
                __syncthreads();
            }
        }
        g_spt[bid][tid] = s_a[tid];
        // inclusive scan over first cnt sorted values
        float x = (tid < cnt) ? s_a[tid] : 0.f;
        #pragma unroll
        for (int o = 1; o < 32; o <<= 1) {
            float y = __shfl_up_sync(0xFFFFFFFFu, x, o);
            if (lane >= o) x += y;
        }
        if (lane == 31) s_wf[wid] = x;
        __syncthreads();
        if (wid == 0) {
            float z = (lane < NWARP) ? s_wf[lane] : 0.f;
            #pragma unroll
            for (int o = 1; o < NWARP; o <<= 1) {
                float y = __shfl_up_sync(0xFFFFFFFFu, z, o);
                if (lane >= o) z += y;
            }
            if (lane < NWARP) s_wf[lane] = z;
        }
        __syncthreads();
        x += (wid > 0) ? s_wf[wid - 1] : 0.f;
        g_pfx[bid][tid + 1] = x;
        if (tid == 0) g_pfx[bid][0] = 0.f;
    }

    // ---- grid barrier 3 ----
    __syncthreads();
    if (tid == 0) { __threadfence(); atomicAdd(&g_bar, 1u);
        while (*(volatile unsigned*)&g_bar < 3u * NBLK) {} __threadfence(); }
    __syncthreads();

    // ================= phase 4: triangular tile pairs ======================
    double acc = 0.0;
    for (int tp = bid; tp < T; tp += (int)NBLK) {
        double disc = (double)(2*G+1) * (double)(2*G+1) - 8.0 * (double)tp;
        int r = (int)(((double)(2*G+1) - sqrt(disc)) * 0.5);
        while (r > 0 && (r*G - (r*(r-1))/2) > tp) --r;
        while (((r+1)*G - ((r+1)*r)/2) <= tp) ++r;
        const int c = r + (tp - (r*G - (r*(r-1))/2));

        const int cbase = c * TILE;
        const int cnt = min(TILE, n - cbase);

        __syncthreads();   // protect smem reuse across iterations
        if (tid < cnt) { s_rp[tid] = g_ps[cbase + tid]; s_rt[tid] = g_tt[cbase + tid]; }
        s_a[tid]   = g_spt[c][tid];
        s_pfx[tid] = g_pfx[c][tid];
        if (tid == 0) s_pfx[TILE] = g_pfx[c][TILE];
        const float tmn = g_tmn[c], tmx = g_tmx[c];
        __syncthreads();

        const int i = r * TILE + tid;
        if (i < n) {
            const float p0 = g_ps[i], t0 = g_tt[i];
            if (r == c) {
                // diagonal: exact masked scalar (j > i within tile)
                float acch = 0.f, accm = 0.f;
                for (int k = tid + 1; k < cnt; k++) {
                    float dp = p0 - s_rp[k];
                    float dt = t0 - s_rt[k];
                    float u = __uint_as_float(__float_as_uint(dp) ^
                              (__float_as_uint(dt) & 0x80000000u));
                    float h = fmaxf(MARGIN - u, 0.f);
                    if (fabsf(dt) > MARGIN) acch += h; else accm += fabsf(dp);
                }
                acc += (double)acch + 0.1 * (double)accm;
            } else {
                const float dtmax = t0 - tmn;   // fl upper bound on every dt
                const float dtmin = t0 - tmx;   // fl lower bound on every dt
                if (dtmin > MARGIN) {
                    // pure hi: s = #{v : fl(p0 - v) >= m}  (exact predicate)
                    int s = 0;
                    #pragma unroll
                    for (int w = 128; w > 0; w >>= 1) {
                        int t2 = s + w;
                        if (t2 <= cnt && (p0 - s_a[t2 - 1] >= MARGIN)) s = t2;
                    }
                    float Ptot = s_pfx[cnt];
                    acc += (double)((float)(cnt - s) * (MARGIN - p0) +
                                    (Ptot - s_pfx[s]));
                } else if (dtmax < -MARGIN) {
                    // pure lo: s = #{v : fl(p0 - v) > -m}
                    int s = 0;
                    #pragma unroll
                    for (int w = 128; w > 0; w >>= 1) {
                        int t2 = s + w;
                        if (t2 <= cnt && (p0 - s_a[t2 - 1] > -MARGIN)) s = t2;
                    }
                    acc += (double)((float)s * (MARGIN + p0) - s_pfx[s]);
                } else if (dtmax <= MARGIN && dtmin >= -MARGIN) {
                    // pure mid: 0.1 * sum |p0 - v| via split at p0
                    int s = 0;
                    #pragma unroll
                    for (int w = 128; w > 0; w >>= 1) {
                        int t2 = s + w;
                        if (t2 <= cnt && (s_a[t2 - 1] <= p0)) s = t2;
                    }
                    float Ps = s_pfx[s], Ptot = s_pfx[cnt];
                    float below = (float)s * p0 - Ps;
                    float above = (Ptot - Ps) - (float)(cnt - s) * p0;
                    acc += 0.1 * (double)(below + above);
                } else {
                    // boundary tile: reference-exact scalar fallback
                    float acch = 0.f, accm = 0.f;
                    #pragma unroll 4
                    for (int k = 0; k < cnt; k++) {
                        float dp = p0 - s_rp[k];
                        float dt = t0 - s_rt[k];
                        float u = __uint_as_float(__float_as_uint(dp) ^
                                  (__float_as_uint(dt) & 0x80000000u));
                        float h = fmaxf(MARGIN - u, 0.f);
                        if (fabsf(dt) > MARGIN) acch += h; else accm += fabsf(dp);
                    }
                    acc += (double)acch + 0.1 * (double)accm;
                }
            }
        }
    }

    // ---- block reduce + one atomic per block ----
    #pragma unroll
    for (int o = 16; o > 0; o >>= 1)
        acc += __shfl_down_sync(0xFFFFFFFFu, acc, o);
    if (lane == 0) s_wd[wid] = acc;
    __syncthreads();
    if (wid == 0) {
        double v = (lane < NWARP) ? s_wd[lane] : 0.0;
        #pragma unroll
        for (int o = 4; o > 0; o >>= 1)
            v += __shfl_down_sync(0xFFFFFFFFu, v, o);
        if (lane == 0) atomicAdd(&g_rank_sum, v);
    }

    // ---- last-block finalize + reset ----
    if (tid == 0) {
        __threadfence();
        unsigned prev = atomicAdd(&g_done, 1u);
        if (prev == NBLK - 1u) {
            double sm = g_m[0], sp2 = g_m[1], st = g_m[2], st2 = g_m[3], sd2 = g_m[4];
            double nn = (double)n;
            double mse  = sd2 / nn;
            double pvar = (sp2 - sm * sm / nn) / (nn - 1.0);
            double tvar = (st2 - st * st / nn) / (nn - 1.0);
            double divl = fmax(tvar - pvar, 0.0);
            double pc   = nn * (nn - 1.0) * 0.5;
            double rank = g_rank_sum / pc;
            out[0] = (float)(0.1 * mse + 0.9 * rank + 0.1 * divl);
            g_bar = 0u;   // reset barrier counter for next graph replay
        }
    }
}

extern "C" void kernel_launch(void* const* d_in, const int* in_sizes, int n_in,
                              void* d_out, int out_size) {
    const float* pred = (const float*)d_in[0];
    const float* targ = (const float*)d_in[1];
    int n = in_sizes[0];
    int G = (n + TILE - 1) / TILE;
    int T = G * (G + 1) / 2;

    fused_kernel<<<GRIDN, TPB>>>(pred, targ, n, G, T, (float*)d_out);
}